// round 2
// baseline (speedup 1.0000x reference)
#include <cuda_runtime.h>
#include <cstdint>
#include <cstddef>

// ---------------------------------------------------------------------------
//   x[N,256], batch[N] (int32 sorted — JAX default config downcasts int64),
//   W_g1[256,256], W_g2[256,8], W_n1[256,256], b_n1[256], W_n2[256,256], b_n2[256]
//   out[B=1024, 32, 8] fp32
// ---------------------------------------------------------------------------

#define N_MAX 200000

__device__ float g_feats[(size_t)N_MAX * 256]; // 204.8 MB scratch
__device__ float g_alpha[(size_t)N_MAX * 8];   // 6.4 MB scratch

// smem float offsets (K1): As[64*20] Bs[16*256] Hs[64*260] W2s[256*8]
#define K1_AS   0
#define K1_BS   1280
#define K1_HS   5376
#define K1_W2S  22016
#define K1_SMEM 24064   // floats -> 96256 bytes

// smem float offsets (K2): As Bs Hs b1s[256] b2s[256]
#define K2_AS   0
#define K2_BS   1280
#define K2_HS   5376
#define K2_B1S  22016
#define K2_B2S  22272
#define K2_SMEM 22528   // floats -> 90112 bytes

// ---------------------------------------------------------------------------
// Main-loop GEMM: acc (4 rows x 16 cols per thread) += X[m0:m0+64, :] @ W[256,256]
// ---------------------------------------------------------------------------
__device__ __forceinline__ void gemm_global_A(const float* __restrict__ X,
                                              const float* __restrict__ W,
                                              float* __restrict__ As,   // [64][20]
                                              float* __restrict__ Bs,   // [16][256]
                                              float (&acc)[64],
                                              int m0, int n)
{
    const int t  = threadIdx.x;
    const int tx = t & 15;
    const int r0 = (t >> 4) * 4;

    for (int kc = 0; kc < 16; ++kc) {
        const int k0 = kc * 16;
        {
            const int row = t >> 2;
            const int kq  = t & 3;
            const int m   = m0 + row;
            float4 v = make_float4(0.f, 0.f, 0.f, 0.f);
            if (m < n) v = *(const float4*)(X + (size_t)m * 256 + k0 + kq * 4);
            *(float4*)(As + row * 20 + kq * 4) = v;
        }
        #pragma unroll
        for (int q = 0; q < 4; ++q) {
            const int u  = t + q * 256;
            const int kr = u >> 6;
            const int c4 = (u & 63) << 2;
            *(float4*)(Bs + kr * 256 + c4) =
                *(const float4*)(W + (size_t)(k0 + kr) * 256 + c4);
        }
        __syncthreads();
        #pragma unroll
        for (int kk = 0; kk < 16; ++kk) {
            float a0 = As[(r0 + 0) * 20 + kk];
            float a1 = As[(r0 + 1) * 20 + kk];
            float a2 = As[(r0 + 2) * 20 + kk];
            float a3 = As[(r0 + 3) * 20 + kk];
            #pragma unroll
            for (int i = 0; i < 4; ++i) {
                float4 bb = *(float4*)(Bs + kk * 256 + i * 64 + (tx << 2));
                acc[0*16 + i*4 + 0] = fmaf(a0, bb.x, acc[0*16 + i*4 + 0]);
                acc[0*16 + i*4 + 1] = fmaf(a0, bb.y, acc[0*16 + i*4 + 1]);
                acc[0*16 + i*4 + 2] = fmaf(a0, bb.z, acc[0*16 + i*4 + 2]);
                acc[0*16 + i*4 + 3] = fmaf(a0, bb.w, acc[0*16 + i*4 + 3]);
                acc[1*16 + i*4 + 0] = fmaf(a1, bb.x, acc[1*16 + i*4 + 0]);
                acc[1*16 + i*4 + 1] = fmaf(a1, bb.y, acc[1*16 + i*4 + 1]);
                acc[1*16 + i*4 + 2] = fmaf(a1, bb.z, acc[1*16 + i*4 + 2]);
                acc[1*16 + i*4 + 3] = fmaf(a1, bb.w, acc[1*16 + i*4 + 3]);
                acc[2*16 + i*4 + 0] = fmaf(a2, bb.x, acc[2*16 + i*4 + 0]);
                acc[2*16 + i*4 + 1] = fmaf(a2, bb.y, acc[2*16 + i*4 + 1]);
                acc[2*16 + i*4 + 2] = fmaf(a2, bb.z, acc[2*16 + i*4 + 2]);
                acc[2*16 + i*4 + 3] = fmaf(a2, bb.w, acc[2*16 + i*4 + 3]);
                acc[3*16 + i*4 + 0] = fmaf(a3, bb.x, acc[3*16 + i*4 + 0]);
                acc[3*16 + i*4 + 1] = fmaf(a3, bb.y, acc[3*16 + i*4 + 1]);
                acc[3*16 + i*4 + 2] = fmaf(a3, bb.z, acc[3*16 + i*4 + 2]);
                acc[3*16 + i*4 + 3] = fmaf(a3, bb.w, acc[3*16 + i*4 + 3]);
            }
        }
        __syncthreads();
    }
}

// Second-stage GEMM: A in smem Hs[64][260], B streamed from global.
__device__ __forceinline__ void gemm_smem_A(const float* __restrict__ Hs,
                                            const float* __restrict__ W,
                                            float* __restrict__ Bs,
                                            float (&acc)[64])
{
    const int t  = threadIdx.x;
    const int tx = t & 15;
    const int r0 = (t >> 4) * 4;

    for (int kc = 0; kc < 16; ++kc) {
        const int k0 = kc * 16;
        #pragma unroll
        for (int q = 0; q < 4; ++q) {
            const int u  = t + q * 256;
            const int kr = u >> 6;
            const int c4 = (u & 63) << 2;
            *(float4*)(Bs + kr * 256 + c4) =
                *(const float4*)(W + (size_t)(k0 + kr) * 256 + c4);
        }
        __syncthreads();
        #pragma unroll
        for (int kk = 0; kk < 16; ++kk) {
            float a0 = Hs[(r0 + 0) * 260 + k0 + kk];
            float a1 = Hs[(r0 + 1) * 260 + k0 + kk];
            float a2 = Hs[(r0 + 2) * 260 + k0 + kk];
            float a3 = Hs[(r0 + 3) * 260 + k0 + kk];
            #pragma unroll
            for (int i = 0; i < 4; ++i) {
                float4 bb = *(float4*)(Bs + kk * 256 + i * 64 + (tx << 2));
                acc[0*16 + i*4 + 0] = fmaf(a0, bb.x, acc[0*16 + i*4 + 0]);
                acc[0*16 + i*4 + 1] = fmaf(a0, bb.y, acc[0*16 + i*4 + 1]);
                acc[0*16 + i*4 + 2] = fmaf(a0, bb.z, acc[0*16 + i*4 + 2]);
                acc[0*16 + i*4 + 3] = fmaf(a0, bb.w, acc[0*16 + i*4 + 3]);
                acc[1*16 + i*4 + 0] = fmaf(a1, bb.x, acc[1*16 + i*4 + 0]);
                acc[1*16 + i*4 + 1] = fmaf(a1, bb.y, acc[1*16 + i*4 + 1]);
                acc[1*16 + i*4 + 2] = fmaf(a1, bb.z, acc[1*16 + i*4 + 2]);
                acc[1*16 + i*4 + 3] = fmaf(a1, bb.w, acc[1*16 + i*4 + 3]);
                acc[2*16 + i*4 + 0] = fmaf(a2, bb.x, acc[2*16 + i*4 + 0]);
                acc[2*16 + i*4 + 1] = fmaf(a2, bb.y, acc[2*16 + i*4 + 1]);
                acc[2*16 + i*4 + 2] = fmaf(a2, bb.z, acc[2*16 + i*4 + 2]);
                acc[2*16 + i*4 + 3] = fmaf(a2, bb.w, acc[2*16 + i*4 + 3]);
                acc[3*16 + i*4 + 0] = fmaf(a3, bb.x, acc[3*16 + i*4 + 0]);
                acc[3*16 + i*4 + 1] = fmaf(a3, bb.y, acc[3*16 + i*4 + 1]);
                acc[3*16 + i*4 + 2] = fmaf(a3, bb.z, acc[3*16 + i*4 + 2]);
                acc[3*16 + i*4 + 3] = fmaf(a3, bb.w, acc[3*16 + i*4 + 3]);
            }
        }
        __syncthreads();
    }
}

// ---------------------------------------------------------------------------
// K1: alpha = relu(x @ W_g1) @ W_g2  -> g_alpha[N,8]
// ---------------------------------------------------------------------------
__global__ __launch_bounds__(256, 2)
void k_gate(const float* __restrict__ x,
            const float* __restrict__ Wg1,
            const float* __restrict__ Wg2,
            int n)
{
    extern __shared__ float sm[];
    float* As  = sm + K1_AS;
    float* Bs  = sm + K1_BS;
    float* Hs  = sm + K1_HS;
    float* W2s = sm + K1_W2S;

    const int t  = threadIdx.x;
    const int tx = t & 15;
    const int r0 = (t >> 4) * 4;
    const int m0 = blockIdx.x * 64;

    #pragma unroll
    for (int q = 0; q < 8; ++q) W2s[t + q * 256] = Wg2[t + q * 256];

    float acc[64];
    #pragma unroll
    for (int i = 0; i < 64; ++i) acc[i] = 0.f;

    gemm_global_A(x, Wg1, As, Bs, acc, m0, n);

    #pragma unroll
    for (int rr = 0; rr < 4; ++rr)
        #pragma unroll
        for (int i = 0; i < 4; ++i) {
            float4 v;
            v.x = fmaxf(acc[rr*16 + i*4 + 0], 0.f);
            v.y = fmaxf(acc[rr*16 + i*4 + 1], 0.f);
            v.z = fmaxf(acc[rr*16 + i*4 + 2], 0.f);
            v.w = fmaxf(acc[rr*16 + i*4 + 3], 0.f);
            *(float4*)(Hs + (r0 + rr) * 260 + i * 64 + (tx << 2)) = v;
        }
    __syncthreads();

    #pragma unroll
    for (int e = 0; e < 2; ++e) {
        const int idx = t + e * 256;
        const int row = idx >> 3;
        const int h   = idx & 7;
        float s = 0.f;
        #pragma unroll 8
        for (int k = 0; k < 256; ++k)
            s = fmaf(Hs[row * 260 + k], W2s[k * 8 + h], s);
        const int m = m0 + row;
        if (m < n) g_alpha[(size_t)m * 8 + h] = s;
    }
}

// ---------------------------------------------------------------------------
// K2: feats = relu(x @ W_n1 + b1) @ W_n2 + b2 -> g_feats[N,256]
// ---------------------------------------------------------------------------
__global__ __launch_bounds__(256, 2)
void k_feat(const float* __restrict__ x,
            const float* __restrict__ Wn1,
            const float* __restrict__ bn1,
            const float* __restrict__ Wn2,
            const float* __restrict__ bn2,
            int n)
{
    extern __shared__ float sm[];
    float* As  = sm + K2_AS;
    float* Bs  = sm + K2_BS;
    float* Hs  = sm + K2_HS;
    float* b1s = sm + K2_B1S;
    float* b2s = sm + K2_B2S;

    const int t  = threadIdx.x;
    const int tx = t & 15;
    const int r0 = (t >> 4) * 4;
    const int m0 = blockIdx.x * 64;

    b1s[t] = bn1[t];
    b2s[t] = bn2[t];

    float acc[64];
    #pragma unroll
    for (int i = 0; i < 64; ++i) acc[i] = 0.f;

    gemm_global_A(x, Wn1, As, Bs, acc, m0, n);

    #pragma unroll
    for (int rr = 0; rr < 4; ++rr)
        #pragma unroll
        for (int i = 0; i < 4; ++i) {
            const int cb = i * 64 + (tx << 2);
            float4 v;
            v.x = fmaxf(acc[rr*16 + i*4 + 0] + b1s[cb + 0], 0.f);
            v.y = fmaxf(acc[rr*16 + i*4 + 1] + b1s[cb + 1], 0.f);
            v.z = fmaxf(acc[rr*16 + i*4 + 2] + b1s[cb + 2], 0.f);
            v.w = fmaxf(acc[rr*16 + i*4 + 3] + b1s[cb + 3], 0.f);
            *(float4*)(Hs + (r0 + rr) * 260 + i * 64 + (tx << 2)) = v;
        }
    __syncthreads();

    #pragma unroll
    for (int rr = 0; rr < 4; ++rr)
        #pragma unroll
        for (int i = 0; i < 4; ++i) {
            const int cb = i * 64 + (tx << 2);
            acc[rr*16 + i*4 + 0] = b2s[cb + 0];
            acc[rr*16 + i*4 + 1] = b2s[cb + 1];
            acc[rr*16 + i*4 + 2] = b2s[cb + 2];
            acc[rr*16 + i*4 + 3] = b2s[cb + 3];
        }

    gemm_smem_A(Hs, Wn2, Bs, acc);

    #pragma unroll
    for (int rr = 0; rr < 4; ++rr) {
        const int m = m0 + r0 + rr;
        if (m < n) {
            #pragma unroll
            for (int i = 0; i < 4; ++i) {
                float4 v;
                v.x = acc[rr*16 + i*4 + 0];
                v.y = acc[rr*16 + i*4 + 1];
                v.z = acc[rr*16 + i*4 + 2];
                v.w = acc[rr*16 + i*4 + 3];
                *(float4*)(g_feats + (size_t)m * 256 + i * 64 + (tx << 2)) = v;
            }
        }
    }
}

// ---------------------------------------------------------------------------
// K3: per-graph softmax over alpha (per head) + gated segment sum of feats.
// ---------------------------------------------------------------------------
__global__ __launch_bounds__(256)
void k_pool(const int* __restrict__ batch,
            float* __restrict__ out,
            int n)
{
    const int b = blockIdx.x;
    const int t = threadIdx.x;

    // binary-search segment bounds in sorted int32 batch
    int lo, hi;
    {
        int l = 0, r = n;
        while (l < r) { int mid = (l + r) >> 1; if (batch[mid] < b) l = mid + 1; else r = mid; }
        lo = l;
        r = n;
        while (l < r) { int mid = (l + r) >> 1; if (batch[mid] < b + 1) l = mid + 1; else r = mid; }
        hi = l;
    }

    __shared__ float red[256][8];
    __shared__ float mh[8];
    __shared__ float sh[8];

    // ---- per-head max ----
    float lm[8];
    #pragma unroll
    for (int q = 0; q < 8; ++q) lm[q] = -1e30f;
    for (int i = lo + t; i < hi; i += 256) {
        #pragma unroll
        for (int q = 0; q < 8; ++q)
            lm[q] = fmaxf(lm[q], g_alpha[(size_t)i * 8 + q]);
    }
    #pragma unroll
    for (int q = 0; q < 8; ++q) red[t][q] = lm[q];
    __syncthreads();
    for (int s2 = 128; s2 > 0; s2 >>= 1) {
        if (t < s2) {
            #pragma unroll
            for (int q = 0; q < 8; ++q)
                red[t][q] = fmaxf(red[t][q], red[t + s2][q]);
        }
        __syncthreads();
    }
    if (t < 8) mh[t] = red[0][t];
    __syncthreads();

    float m8[8];
    #pragma unroll
    for (int q = 0; q < 8; ++q) m8[q] = mh[q];

    // ---- per-head sum of exp ----
    float ls[8];
    #pragma unroll
    for (int q = 0; q < 8; ++q) ls[q] = 0.f;
    for (int i = lo + t; i < hi; i += 256) {
        #pragma unroll
        for (int q = 0; q < 8; ++q)
            ls[q] += __expf(g_alpha[(size_t)i * 8 + q] - m8[q]);
    }
    __syncthreads();
    #pragma unroll
    for (int q = 0; q < 8; ++q) red[t][q] = ls[q];
    __syncthreads();
    for (int s2 = 128; s2 > 0; s2 >>= 1) {
        if (t < s2) {
            #pragma unroll
            for (int q = 0; q < 8; ++q)
                red[t][q] += red[t + s2][q];
        }
        __syncthreads();
    }
    if (t < 8) sh[t] = red[0][t];
    __syncthreads();

    // ---- gated accumulation; thread t owns output column t (h = t&7) ----
    const int h = t & 7;
    const float mm  = mh[h];
    const float inv = 1.f / (sh[h] + 1e-16f);

    float acc = 0.f;
    #pragma unroll 4
    for (int i = lo; i < hi; ++i) {
        const float g = __expf(g_alpha[(size_t)i * 8 + h] - mm) * inv;
        acc = fmaf(g, g_feats[(size_t)i * 256 + t], acc);
    }
    out[(size_t)b * 256 + t] = acc;
}

// ---------------------------------------------------------------------------
extern "C" void kernel_launch(void* const* d_in, const int* in_sizes, int n_in,
                              void* d_out, int out_size)
{
    const float* x     = (const float*)d_in[0];
    const int*   batch = (const int*)d_in[1];
    const float* Wg1   = (const float*)d_in[2];
    const float* Wg2   = (const float*)d_in[3];
    const float* Wn1   = (const float*)d_in[4];
    const float* bn1   = (const float*)d_in[5];
    const float* Wn2   = (const float*)d_in[6];
    const float* bn2   = (const float*)d_in[7];
    float* out = (float*)d_out;

    const int n = in_sizes[0] / 256;
    const int B = out_size / 256;
    const int blocks = (n + 63) / 64;

    cudaFuncSetAttribute(k_gate, cudaFuncAttributeMaxDynamicSharedMemorySize, K1_SMEM * 4);
    cudaFuncSetAttribute(k_feat, cudaFuncAttributeMaxDynamicSharedMemorySize, K2_SMEM * 4);

    k_gate<<<blocks, 256, K1_SMEM * 4>>>(x, Wg1, Wg2, n);
    k_feat<<<blocks, 256, K2_SMEM * 4>>>(x, Wn1, bn1, Wn2, bn2, n);
    k_pool<<<B, 256>>>(batch, out, n);
}

// round 4
// speedup vs baseline: 2.7276x; 2.7276x over previous
#include <cuda_runtime.h>
#include <cuda_bf16.h>
#include <cstdint>
#include <cstddef>

// ---------------------------------------------------------------------------
//   x[N,256], batch[N] int32 sorted, W_g1[256,256], W_g2[256,8],
//   W_n1[256,256], b_n1[256], W_n2[256,256], b_n2[256] -> out[1024,256] fp32
//   Engine: mma.sync m16n8k16 bf16 (compute_103-safe), hi/lo 3-pass split.
// ---------------------------------------------------------------------------

#define N_MAX 200000

__device__ float g_feats[(size_t)N_MAX * 256];  // 204.8 MB scratch
__device__ float g_alpha[(size_t)N_MAX * 8];    // 6.4 MB scratch
// fragment-ordered weights: [w(3)][hl(2)][kstep(16)][nfrag(32)][lane(32)] uint2
__device__ uint2 g_Wfrag[3 * 2 * 16 * 32 * 32];

// ---------------- helpers ----------------------------------------------------
__device__ __forceinline__ uint32_t smem_u32(const void* p) {
    uint32_t a;
    asm("{ .reg .u64 t; cvta.to.shared.u64 t, %1; cvt.u32.u64 %0, t; }"
        : "=r"(a) : "l"(p));
    return a;
}
__device__ __forceinline__ uint32_t pack_bf16(float a, float b) {
    __nv_bfloat162 t = __floats2bfloat162_rn(a, b);  // low = a
    return *(uint32_t*)&t;
}
__device__ __forceinline__ void split_bf16(float v, float& hi_f, uint16_t& h, uint16_t& l) {
    __nv_bfloat16 hb = __float2bfloat16(v);
    hi_f = __bfloat162float(hb);
    h = __bfloat16_as_ushort(hb);
    l = __bfloat16_as_ushort(__float2bfloat16(v - hi_f));
}
__device__ __forceinline__ void ldsm4(uint32_t* a, uint32_t addr) {
    asm volatile("ldmatrix.sync.aligned.m8n8.x4.shared.b16 {%0,%1,%2,%3}, [%4];"
                 : "=r"(a[0]), "=r"(a[1]), "=r"(a[2]), "=r"(a[3]) : "r"(addr));
}
__device__ __forceinline__ void mma16816(float* c, const uint32_t* a, uint2 b) {
    asm volatile(
        "mma.sync.aligned.m16n8k16.row.col.f32.bf16.bf16.f32 "
        "{%0,%1,%2,%3},{%4,%5,%6,%7},{%8,%9},{%0,%1,%2,%3};"
        : "+f"(c[0]), "+f"(c[1]), "+f"(c[2]), "+f"(c[3])
        : "r"(a[0]), "r"(a[1]), "r"(a[2]), "r"(a[3]), "r"(b.x), "r"(b.y));
}

// ---------------- smem layout (bytes) for k_main ----------------------------
// A1 hi [64 rows x 64k bf16, pitch 72 elems=144B] : 0      .. 9216
// A1 lo                                           : 9216   .. 18432
// Hh[4 chunks]                                    : 18432  .. 55296
// Hl[4 chunks]                                    : 55296  .. 92160
// Wg2s fp32 [256][8]                              : 92160  .. 100352
// b1s fp32 [256]                                  : 100352 .. 101376
// b2s fp32 [256]                                  : 101376 .. 102400
// alpha_sm fp32 [64][8]                           : 102400 .. 104448
#define OFF_A1H   0
#define OFF_A1L   9216
#define OFF_HH    18432
#define OFF_HL    55296
#define OFF_WG2   92160
#define OFF_B1    100352
#define OFF_B2    101376
#define OFF_ALPHA 102400
#define SMEM_BYTES 104448

// ---------------------------------------------------------------------------
// k_prep: pack W (3 weights) into fragment-ordered bf16 hi/lo uint2 arrays.
// B frag (m16n8k16, col-major k x n): lane: n = nf*8 + (lane>>2),
//   reg0 = {B[k0][n], B[k0+1][n]}, reg1 = {B[k0+8][n], B[k0+9][n]},
//   k0 = ks*16 + (lane&3)*2, with B[k][n] = W[k][n] (W row-major [k][n]).
// ---------------------------------------------------------------------------
__global__ void k_prep(const float* __restrict__ Wn1,
                       const float* __restrict__ Wg1,
                       const float* __restrict__ Wn2)
{
    const float* W = (blockIdx.y == 0) ? Wn1 : (blockIdx.y == 1) ? Wg1 : Wn2;
    const int i = blockIdx.x * 256 + threadIdx.x;   // 0..16383
    const int lane = i & 31;
    const int nf   = (i >> 5) & 31;
    const int ks   = i >> 10;                       // 0..15
    const int nn   = nf * 8 + (lane >> 2);
    const int k0   = ks * 16 + (lane & 3) * 2;

    float v[4];
    v[0] = W[(k0 + 0) * 256 + nn];
    v[1] = W[(k0 + 1) * 256 + nn];
    v[2] = W[(k0 + 8) * 256 + nn];
    v[3] = W[(k0 + 9) * 256 + nn];

    uint16_t h[4], l[4];
    #pragma unroll
    for (int q = 0; q < 4; ++q) {
        float hf; split_bf16(v[q], hf, h[q], l[q]);
    }
    uint2 hi, lo;
    hi.x = (uint32_t)h[0] | ((uint32_t)h[1] << 16);
    hi.y = (uint32_t)h[2] | ((uint32_t)h[3] << 16);
    lo.x = (uint32_t)l[0] | ((uint32_t)l[1] << 16);
    lo.y = (uint32_t)l[2] | ((uint32_t)l[3] << 16);

    const int w = blockIdx.y;
    g_Wfrag[((((w * 2 + 0) * 16 + ks) * 32 + nf) * 32) + lane] = hi;
    g_Wfrag[((((w * 2 + 1) * 16 + ks) * 32 + nf) * 32) + lane] = lo;
}

// ---------------------------------------------------------------------------
// k_main: 64-row tile, 512 threads (16 warps).
// stage1: warps (mw = w&1 row-half, nw = w>>1): nw 0..3 -> x@Wn1 (cols 0..255),
//         nw 4..7 -> x@Wg1. Warp tile 32x64.
// gate epi -> alpha_sm -> g_alpha ; feat epi -> H bf16 hi/lo smem
// stage2: warps (mw2 = w&3 16-row quarter, nw2 = w>>2 col slice): H@Wn2 +b2.
// ---------------------------------------------------------------------------
__global__ __launch_bounds__(512, 1)
void k_main(const float* __restrict__ x,
            const float* __restrict__ Wg2,
            const float* __restrict__ bn1,
            const float* __restrict__ bn2,
            int n)
{
    extern __shared__ unsigned char sm[];
    const uint32_t sb = smem_u32(sm);
    float* Wg2s     = (float*)(sm + OFF_WG2);
    float* b1s      = (float*)(sm + OFF_B1);
    float* b2s      = (float*)(sm + OFF_B2);
    float* alpha_sm = (float*)(sm + OFF_ALPHA);

    const int t = threadIdx.x;
    const int lane = t & 31, w = t >> 5;
    const int g = lane >> 2, tig = lane & 3;
    const int m0 = blockIdx.x * 64;

    // init smem
    #pragma unroll
    for (int q = 0; q < 4; ++q) Wg2s[t + q * 512] = Wg2[t + q * 512];
    if (t < 256) { b1s[t] = bn1[t]; b2s[t] = bn2[t]; }
    alpha_sm[t] = 0.f;
    __syncthreads();

    // ===================== stage 1 =====================
    const int mw = w & 1, nw = w >> 1;
    const int wid1 = (nw >= 4) ? 1 : 0;
    const int nbase = (nw & 3) * 8;

    float acc[8][2][4];
    #pragma unroll
    for (int j = 0; j < 8; ++j)
        #pragma unroll
        for (int mf = 0; mf < 2; ++mf)
            #pragma unroll
            for (int q = 0; q < 4; ++q) acc[j][mf][q] = 0.f;

    for (int kc = 0; kc < 4; ++kc) {
        // stage A chunk: x[m0:m0+64, kc*64:+64] -> bf16 hi/lo smem
        #pragma unroll
        for (int e = 0; e < 2; ++e) {
            const int idx = t + e * 512;          // 0..1023
            const int row = idx >> 4, q = idx & 15;
            const int m = m0 + row;
            float4 v = make_float4(0.f, 0.f, 0.f, 0.f);
            if (m < n) v = ((const float4*)(x + (size_t)m * 256 + kc * 64))[q];
            float hf; uint16_t h0, h1, h2, h3, l0, l1, l2, l3;
            split_bf16(v.x, hf, h0, l0);
            split_bf16(v.y, hf, h1, l1);
            split_bf16(v.z, hf, h2, l2);
            split_bf16(v.w, hf, h3, l3);
            uint2 hp, lp;
            hp.x = (uint32_t)h0 | ((uint32_t)h1 << 16);
            hp.y = (uint32_t)h2 | ((uint32_t)h3 << 16);
            lp.x = (uint32_t)l0 | ((uint32_t)l1 << 16);
            lp.y = (uint32_t)l2 | ((uint32_t)l3 << 16);
            *(uint2*)(sm + OFF_A1H + row * 144 + q * 8) = hp;
            *(uint2*)(sm + OFF_A1L + row * 144 + q * 8) = lp;
        }
        __syncthreads();

        #pragma unroll
        for (int ks = 0; ks < 4; ++ks) {
            const uint32_t abase = sb + (mw * 32 + (lane & 15)) * 144
                                   + ks * 32 + ((lane >> 4) << 4);
            uint32_t ah0[4], ah1[4], al0[4], al1[4];
            ldsm4(ah0, abase + OFF_A1H);
            ldsm4(ah1, abase + OFF_A1H + 16 * 144);
            ldsm4(al0, abase + OFF_A1L);
            ldsm4(al1, abase + OFF_A1L + 16 * 144);

            const int ksg = kc * 4 + ks;
            const int fb = ((wid1 * 32 + ksg) * 32 + nbase) * 32 + lane;
            #pragma unroll
            for (int j = 0; j < 8; ++j) {
                const uint2 bh = __ldg(&g_Wfrag[fb + j * 32]);
                const uint2 bl = __ldg(&g_Wfrag[fb + 16384 + j * 32]);
                mma16816(acc[j][0], ah0, bh);
                mma16816(acc[j][1], ah1, bh);
                mma16816(acc[j][0], ah0, bl);
                mma16816(acc[j][1], ah1, bl);
                mma16816(acc[j][0], al0, bh);
                mma16816(acc[j][1], al1, bh);
            }
        }
        __syncthreads();
    }

    // ===================== stage-1 epilogues =====================
    if (nw >= 4) {
        // gate: alpha partial = relu(D) @ Wg2 over this warp's 64-col slice
        const int c0 = (nw - 4) * 64;
        float pa[4][8];
        #pragma unroll
        for (int s = 0; s < 4; ++s)
            #pragma unroll
            for (int h = 0; h < 8; ++h) pa[s][h] = 0.f;

        #pragma unroll
        for (int mf = 0; mf < 2; ++mf)
            #pragma unroll
            for (int j = 0; j < 8; ++j) {
                const int c = c0 + j * 8 + tig * 2;
                const float d0 = fmaxf(acc[j][mf][0], 0.f);
                const float d1 = fmaxf(acc[j][mf][1], 0.f);
                const float d2 = fmaxf(acc[j][mf][2], 0.f);
                const float d3 = fmaxf(acc[j][mf][3], 0.f);
                const float4* wa = (const float4*)(Wg2s + c * 8);
                const float4* wb = (const float4*)(Wg2s + (c + 1) * 8);
                const float4 a0 = wa[0], a1 = wa[1], b0 = wb[0], b1 = wb[1];
                float* p0 = pa[mf * 2];
                float* p1 = pa[mf * 2 + 1];
                p0[0] = fmaf(d0, a0.x, fmaf(d1, b0.x, p0[0]));
                p0[1] = fmaf(d0, a0.y, fmaf(d1, b0.y, p0[1]));
                p0[2] = fmaf(d0, a0.z, fmaf(d1, b0.z, p0[2]));
                p0[3] = fmaf(d0, a0.w, fmaf(d1, b0.w, p0[3]));
                p0[4] = fmaf(d0, a1.x, fmaf(d1, b1.x, p0[4]));
                p0[5] = fmaf(d0, a1.y, fmaf(d1, b1.y, p0[5]));
                p0[6] = fmaf(d0, a1.z, fmaf(d1, b1.z, p0[6]));
                p0[7] = fmaf(d0, a1.w, fmaf(d1, b1.w, p0[7]));
                p1[0] = fmaf(d2, a0.x, fmaf(d3, b0.x, p1[0]));
                p1[1] = fmaf(d2, a0.y, fmaf(d3, b0.y, p1[1]));
                p1[2] = fmaf(d2, a0.z, fmaf(d3, b0.z, p1[2]));
                p1[3] = fmaf(d2, a0.w, fmaf(d3, b0.w, p1[3]));
                p1[4] = fmaf(d2, a1.x, fmaf(d3, b1.x, p1[4]));
                p1[5] = fmaf(d2, a1.y, fmaf(d3, b1.y, p1[5]));
                p1[6] = fmaf(d2, a1.z, fmaf(d3, b1.z, p1[6]));
                p1[7] = fmaf(d2, a1.w, fmaf(d3, b1.w, p1[7]));
            }
        // quad butterfly (lanes sharing the same rows differ only in tig)
        #pragma unroll
        for (int off = 1; off <= 2; off <<= 1)
            #pragma unroll
            for (int s = 0; s < 4; ++s)
                #pragma unroll
                for (int h = 0; h < 8; ++h)
                    pa[s][h] += __shfl_xor_sync(0xffffffffu, pa[s][h], off);
        if (tig == 0) {
            #pragma unroll
            for (int s = 0; s < 4; ++s) {
                const int row = mw * 32 + (s >> 1) * 16 + (s & 1) * 8 + g;
                #pragma unroll
                for (int h = 0; h < 8; ++h)
                    atomicAdd(&alpha_sm[row * 8 + h], pa[s][h]);
            }
        }
    } else {
        // feat: H = relu(D + b1) -> bf16 hi/lo into chunk nw of H smem
        const int kcH = nw;                    // this warp's 64-col slice == chunk
        unsigned char* Hh = sm + OFF_HH + kcH * 9216;
        unsigned char* Hl = sm + OFF_HL + kcH * 9216;
        #pragma unroll
        for (int mf = 0; mf < 2; ++mf)
            #pragma unroll
            for (int j = 0; j < 8; ++j) {
                const int ci = j * 8 + tig * 2;             // col within chunk
                const int c  = kcH * 64 + ci;
                const int r0 = mw * 32 + mf * 16 + g;
                const int r1 = r0 + 8;
                const float v0 = fmaxf(acc[j][mf][0] + b1s[c], 0.f);
                const float v1 = fmaxf(acc[j][mf][1] + b1s[c + 1], 0.f);
                const float v2 = fmaxf(acc[j][mf][2] + b1s[c], 0.f);
                const float v3 = fmaxf(acc[j][mf][3] + b1s[c + 1], 0.f);
                float hf; uint16_t h0, h1, h2, h3, l0, l1, l2, l3;
                split_bf16(v0, hf, h0, l0);
                split_bf16(v1, hf, h1, l1);
                split_bf16(v2, hf, h2, l2);
                split_bf16(v3, hf, h3, l3);
                *(uint32_t*)(Hh + r0 * 144 + ci * 2) = (uint32_t)h0 | ((uint32_t)h1 << 16);
                *(uint32_t*)(Hl + r0 * 144 + ci * 2) = (uint32_t)l0 | ((uint32_t)l1 << 16);
                *(uint32_t*)(Hh + r1 * 144 + ci * 2) = (uint32_t)h2 | ((uint32_t)h3 << 16);
                *(uint32_t*)(Hl + r1 * 144 + ci * 2) = (uint32_t)l2 | ((uint32_t)l3 << 16);
            }
    }
    __syncthreads();

    // write alpha
    {
        const int row = t >> 3, h = t & 7;
        const int m = m0 + row;
        if (m < n) g_alpha[(size_t)m * 8 + h] = alpha_sm[row * 8 + h];
    }

    // ===================== stage 2: feats = H @ Wn2 + b2 =====================
    const int mw2 = w & 3, nw2 = w >> 2;
    float acc2[8][4];
    #pragma unroll
    for (int j = 0; j < 8; ++j)
        #pragma unroll
        for (int q = 0; q < 4; ++q) acc2[j][q] = 0.f;

    for (int kc = 0; kc < 4; ++kc) {
        const uint32_t hbase = sb + (mw2 * 16 + (lane & 15)) * 144
                               + ((lane >> 4) << 4) + kc * 9216;
        #pragma unroll
        for (int ks = 0; ks < 4; ++ks) {
            uint32_t ah[4], al[4];
            ldsm4(ah, hbase + OFF_HH + ks * 32);
            ldsm4(al, hbase + OFF_HL + ks * 32);
            const int ksg = kc * 4 + ks;
            const int fb = ((2 * 32 + ksg) * 32 + nw2 * 8) * 32 + lane;
            #pragma unroll
            for (int j = 0; j < 8; ++j) {
                const uint2 bh = __ldg(&g_Wfrag[fb + j * 32]);
                const uint2 bl = __ldg(&g_Wfrag[fb + 16384 + j * 32]);
                mma16816(acc2[j], ah, bh);
                mma16816(acc2[j], ah, bl);
                mma16816(acc2[j], al, bh);
            }
        }
    }

    // feats epilogue
    #pragma unroll
    for (int j = 0; j < 8; ++j) {
        const int c = nw2 * 64 + j * 8 + tig * 2;
        const int r0 = mw2 * 16 + g;
        const int r1 = r0 + 8;
        float2 s0, s1;
        s0.x = acc2[j][0] + b2s[c];
        s0.y = acc2[j][1] + b2s[c + 1];
        s1.x = acc2[j][2] + b2s[c];
        s1.y = acc2[j][3] + b2s[c + 1];
        if (m0 + r0 < n) *(float2*)(g_feats + (size_t)(m0 + r0) * 256 + c) = s0;
        if (m0 + r1 < n) *(float2*)(g_feats + (size_t)(m0 + r1) * 256 + c) = s1;
    }
}

// ---------------------------------------------------------------------------
// k_pool: per-graph softmax over alpha (per head) + gated segment sum of feats
// ---------------------------------------------------------------------------
__global__ __launch_bounds__(256)
void k_pool(const int* __restrict__ batch,
            float* __restrict__ out,
            int n)
{
    const int b = blockIdx.x;
    const int t = threadIdx.x;

    int lo, hi;
    {
        int l = 0, r2 = n;
        while (l < r2) { int mid = (l + r2) >> 1; if (batch[mid] < b) l = mid + 1; else r2 = mid; }
        lo = l;
        r2 = n;
        while (l < r2) { int mid = (l + r2) >> 1; if (batch[mid] < b + 1) l = mid + 1; else r2 = mid; }
        hi = l;
    }

    __shared__ float red[256][8];
    __shared__ float mh[8];
    __shared__ float sh[8];

    float lm[8];
    #pragma unroll
    for (int q = 0; q < 8; ++q) lm[q] = -1e30f;
    for (int i = lo + t; i < hi; i += 256) {
        #pragma unroll
        for (int q = 0; q < 8; ++q)
            lm[q] = fmaxf(lm[q], g_alpha[(size_t)i * 8 + q]);
    }
    #pragma unroll
    for (int q = 0; q < 8; ++q) red[t][q] = lm[q];
    __syncthreads();
    for (int s2 = 128; s2 > 0; s2 >>= 1) {
        if (t < s2) {
            #pragma unroll
            for (int q = 0; q < 8; ++q)
                red[t][q] = fmaxf(red[t][q], red[t + s2][q]);
        }
        __syncthreads();
    }
    if (t < 8) mh[t] = red[0][t];
    __syncthreads();

    float m8[8];
    #pragma unroll
    for (int q = 0; q < 8; ++q) m8[q] = mh[q];

    float ls[8];
    #pragma unroll
    for (int q = 0; q < 8; ++q) ls[q] = 0.f;
    for (int i = lo + t; i < hi; i += 256) {
        #pragma unroll
        for (int q = 0; q < 8; ++q)
            ls[q] += __expf(g_alpha[(size_t)i * 8 + q] - m8[q]);
    }
    __syncthreads();
    #pragma unroll
    for (int q = 0; q < 8; ++q) red[t][q] = ls[q];
    __syncthreads();
    for (int s2 = 128; s2 > 0; s2 >>= 1) {
        if (t < s2) {
            #pragma unroll
            for (int q = 0; q < 8; ++q)
                red[t][q] += red[t + s2][q];
        }
        __syncthreads();
    }
    if (t < 8) sh[t] = red[0][t];
    __syncthreads();

    const int h = t & 7;
    const float mm  = mh[h];
    const float inv = 1.f / (sh[h] + 1e-16f);

    float acc = 0.f;
    #pragma unroll 4
    for (int i = lo; i < hi; ++i) {
        const float g = __expf(g_alpha[(size_t)i * 8 + h] - mm) * inv;
        acc = fmaf(g, g_feats[(size_t)i * 256 + t], acc);
    }
    out[(size_t)b * 256 + t] = acc;
}

// ---------------------------------------------------------------------------
extern "C" void kernel_launch(void* const* d_in, const int* in_sizes, int n_in,
                              void* d_out, int out_size)
{
    const float* x     = (const float*)d_in[0];
    const int*   batch = (const int*)d_in[1];
    const float* Wg1   = (const float*)d_in[2];
    const float* Wg2   = (const float*)d_in[3];
    const float* Wn1   = (const float*)d_in[4];
    const float* bn1   = (const float*)d_in[5];
    const float* Wn2   = (const float*)d_in[6];
    const float* bn2   = (const float*)d_in[7];
    float* out = (float*)d_out;

    const int n = in_sizes[0] / 256;
    const int B = out_size / 256;
    const int tiles = (n + 63) / 64;

    cudaFuncSetAttribute(k_main, cudaFuncAttributeMaxDynamicSharedMemorySize, SMEM_BYTES);

    k_prep<<<dim3(64, 3), 256>>>(Wn1, Wg1, Wn2);
    k_main<<<tiles, 512, SMEM_BYTES>>>(x, Wg2, bn1, bn2, n);
    k_pool<<<B, 256>>>(batch, out, n);
}

// round 5
// speedup vs baseline: 2.9406x; 1.0781x over previous
#include <cuda_runtime.h>
#include <cuda_bf16.h>
#include <cstdint>
#include <cstddef>

// ---------------------------------------------------------------------------
//   x[N,256], batch[N] int32 sorted, W_g1[256,256], W_g2[256,8],
//   W_n1[256,256], b_n1[256], W_n2[256,256], b_n2[256] -> out[1024,256] fp32
//   Engine: mma.sync m16n8k16 bf16 hi/lo 3-pass. Gating fused into feats
//   kernel (no g_feats round-trip): alpha -> stats/gates -> gated tile-reduce.
// ---------------------------------------------------------------------------

#define N_MAX 200000

__device__ float g_alpha[(size_t)N_MAX * 8];    // alpha, then gates (in-place)
// fragment-ordered weights: [w(3)][hl(2)][kstep(16)][nfrag(32)][lane(32)] uint2
__device__ uint2 g_Wfrag[3 * 2 * 16 * 32 * 32];

// ---------------- helpers ---------------------------------------------------
__device__ __forceinline__ uint32_t smem_u32(const void* p) {
    uint32_t a;
    asm("{ .reg .u64 t; cvta.to.shared.u64 t, %1; cvt.u32.u64 %0, t; }"
        : "=r"(a) : "l"(p));
    return a;
}
__device__ __forceinline__ void split_bf16(float v, uint16_t& h, uint16_t& l) {
    __nv_bfloat16 hb = __float2bfloat16(v);
    h = __bfloat16_as_ushort(hb);
    l = __bfloat16_as_ushort(__float2bfloat16(v - __bfloat162float(hb)));
}
__device__ __forceinline__ void ldsm4(uint32_t* a, uint32_t addr) {
    asm volatile("ldmatrix.sync.aligned.m8n8.x4.shared.b16 {%0,%1,%2,%3}, [%4];"
                 : "=r"(a[0]), "=r"(a[1]), "=r"(a[2]), "=r"(a[3]) : "r"(addr));
}
__device__ __forceinline__ void mma16816(float* c, const uint32_t* a, uint2 b) {
    asm volatile(
        "mma.sync.aligned.m16n8k16.row.col.f32.bf16.bf16.f32 "
        "{%0,%1,%2,%3},{%4,%5,%6,%7},{%8,%9},{%0,%1,%2,%3};"
        : "+f"(c[0]), "+f"(c[1]), "+f"(c[2]), "+f"(c[3])
        : "r"(a[0]), "r"(a[1]), "r"(a[2]), "r"(a[3]), "r"(b.x), "r"(b.y));
}

// ---------------- smem layouts (bytes) --------------------------------------
#define P_A 528                    // bf16 tile pitch: 64 rows x 256 cols + pad
#define OFF_AH   0                 // 64*528 = 33792
#define OFF_AL   33792             // 33792 ; A total 67584 (reused for H, Wf)
#define P_WF 1032                  // fp32 weighted-feats pitch (64 x 1032 = 66048)

// k_alpha extras
#define OFF_WG2   67584            // 8192
#define OFF_ALPHA 75776            // 2048
#define SMEM_ALPHA 77824

// k_feat2 extras
#define OFF_B1    67584            // 1024
#define OFF_B2    68608            // 1024
#define OFF_BB    69632            // 256 (batch ids)
#define SMEM_FEAT 69888

// ---------------------------------------------------------------------------
// k_prep: pack 3 weights into fragment-ordered bf16 hi/lo uint2 arrays.
// B frag (m16n8k16 col-major): n = nf*8 + (lane>>2), k0 = ks*16 + (lane&3)*2,
// reg0 = {B[k0][n], B[k0+1][n]}, reg1 = {B[k0+8][n], B[k0+9][n]}.
// ---------------------------------------------------------------------------
__global__ void k_prep(const float* __restrict__ Wn1,
                       const float* __restrict__ Wg1,
                       const float* __restrict__ Wn2)
{
    const float* W = (blockIdx.y == 0) ? Wn1 : (blockIdx.y == 1) ? Wg1 : Wn2;
    const int i = blockIdx.x * 256 + threadIdx.x;
    const int lane = i & 31;
    const int nf   = (i >> 5) & 31;
    const int ks   = i >> 10;
    const int nn   = nf * 8 + (lane >> 2);
    const int k0   = ks * 16 + (lane & 3) * 2;

    float v[4];
    v[0] = W[(k0 + 0) * 256 + nn];
    v[1] = W[(k0 + 1) * 256 + nn];
    v[2] = W[(k0 + 8) * 256 + nn];
    v[3] = W[(k0 + 9) * 256 + nn];

    uint16_t h[4], l[4];
    #pragma unroll
    for (int q = 0; q < 4; ++q) split_bf16(v[q], h[q], l[q]);
    uint2 hi, lo;
    hi.x = (uint32_t)h[0] | ((uint32_t)h[1] << 16);
    hi.y = (uint32_t)h[2] | ((uint32_t)h[3] << 16);
    lo.x = (uint32_t)l[0] | ((uint32_t)l[1] << 16);
    lo.y = (uint32_t)l[2] | ((uint32_t)l[3] << 16);

    const int w = blockIdx.y;
    g_Wfrag[((((w * 2 + 0) * 16 + ks) * 32 + nf) * 32) + lane] = hi;
    g_Wfrag[((((w * 2 + 1) * 16 + ks) * 32 + nf) * 32) + lane] = lo;
}

// stage x[m0:m0+64, 0:256] into bf16 hi/lo smem (pitch P_A)
__device__ __forceinline__ void stage_x(const float* __restrict__ x,
                                        unsigned char* sm, int m0, int n, int t)
{
    #pragma unroll
    for (int e = 0; e < 8; ++e) {
        const int idx = t + e * 512;          // 0..4095 float4s
        const int row = idx >> 6, q = idx & 63;
        const int m = m0 + row;
        float4 v = make_float4(0.f, 0.f, 0.f, 0.f);
        if (m < n) v = ((const float4*)(x + (size_t)m * 256))[q];
        uint16_t h0, h1, h2, h3, l0, l1, l2, l3;
        split_bf16(v.x, h0, l0);
        split_bf16(v.y, h1, l1);
        split_bf16(v.z, h2, l2);
        split_bf16(v.w, h3, l3);
        uint2 hp, lp;
        hp.x = (uint32_t)h0 | ((uint32_t)h1 << 16);
        hp.y = (uint32_t)h2 | ((uint32_t)h3 << 16);
        lp.x = (uint32_t)l0 | ((uint32_t)l1 << 16);
        lp.y = (uint32_t)l2 | ((uint32_t)l3 << 16);
        *(uint2*)(sm + OFF_AH + row * P_A + q * 8) = hp;
        *(uint2*)(sm + OFF_AL + row * P_A + q * 8) = lp;
    }
}

// 3-pass 32x32 warp-tile GEMM vs weight image `wimg`, A in smem at OFF_AH/AL.
// acc[j][mf][4]: rows mw*32 + mf*16 + {g, g+8}, cols nw*32 + j*8 + tig*2 (+1).
__device__ __forceinline__ void gemm_tile(uint32_t sb, int wimg, int mw, int nw,
                                          int lane, float (&acc)[4][2][4])
{
    #pragma unroll
    for (int ks = 0; ks < 16; ++ks) {
        const uint32_t abase = sb + (mw * 32 + (lane & 15)) * P_A
                               + ks * 32 + ((lane >> 4) << 4);
        uint32_t ah0[4], ah1[4], al0[4], al1[4];
        ldsm4(ah0, abase + OFF_AH);
        ldsm4(ah1, abase + OFF_AH + 16 * P_A);
        ldsm4(al0, abase + OFF_AL);
        ldsm4(al1, abase + OFF_AL + 16 * P_A);
        const int fb = ((wimg * 32 + ks) * 32 + nw * 4) * 32 + lane;
        #pragma unroll
        for (int j = 0; j < 4; ++j) {
            const uint2 bh = __ldg(&g_Wfrag[fb + j * 32]);
            const uint2 bl = __ldg(&g_Wfrag[fb + 16384 + j * 32]);
            mma16816(acc[j][0], ah0, bh);
            mma16816(acc[j][1], ah1, bh);
            mma16816(acc[j][0], ah0, bl);
            mma16816(acc[j][1], ah1, bl);
            mma16816(acc[j][0], al0, bh);
            mma16816(acc[j][1], al1, bh);
        }
    }
}

// ---------------------------------------------------------------------------
// k_alpha: alpha = relu(x @ W_g1) @ W_g2 -> g_alpha[N,8]
// ---------------------------------------------------------------------------
__global__ __launch_bounds__(512, 1)
void k_alpha(const float* __restrict__ x,
             const float* __restrict__ Wg2,
             int n)
{
    extern __shared__ unsigned char sm[];
    const uint32_t sb = smem_u32(sm);
    float* Wg2s     = (float*)(sm + OFF_WG2);
    float* alpha_sm = (float*)(sm + OFF_ALPHA);

    const int t = threadIdx.x;
    const int lane = t & 31, w = t >> 5;
    const int g = lane >> 2, tig = lane & 3;
    const int m0 = blockIdx.x * 64;
    const int mw = w & 1, nw = w >> 1;

    #pragma unroll
    for (int q = 0; q < 4; ++q) Wg2s[t + q * 512] = Wg2[t + q * 512];
    alpha_sm[t] = 0.f;
    stage_x(x, sm, m0, n, t);
    __syncthreads();

    float acc[4][2][4];
    #pragma unroll
    for (int j = 0; j < 4; ++j)
        #pragma unroll
        for (int mf = 0; mf < 2; ++mf)
            #pragma unroll
            for (int q = 0; q < 4; ++q) acc[j][mf][q] = 0.f;

    gemm_tile(sb, 1, mw, nw, lane, acc);   // image 1 = W_g1

    // gate epilogue: relu(D) @ Wg2 over this warp's 32-col slice
    float pa[4][8];
    #pragma unroll
    for (int s = 0; s < 4; ++s)
        #pragma unroll
        for (int h = 0; h < 8; ++h) pa[s][h] = 0.f;

    #pragma unroll
    for (int mf = 0; mf < 2; ++mf)
        #pragma unroll
        for (int j = 0; j < 4; ++j) {
            const int c = nw * 32 + j * 8 + tig * 2;
            const float d0 = fmaxf(acc[j][mf][0], 0.f);
            const float d1 = fmaxf(acc[j][mf][1], 0.f);
            const float d2 = fmaxf(acc[j][mf][2], 0.f);
            const float d3 = fmaxf(acc[j][mf][3], 0.f);
            const float4* wa = (const float4*)(Wg2s + c * 8);
            const float4* wb = (const float4*)(Wg2s + (c + 1) * 8);
            const float4 a0 = wa[0], a1 = wa[1], b0 = wb[0], b1 = wb[1];
            float* p0 = pa[mf * 2];
            float* p1 = pa[mf * 2 + 1];
            p0[0] = fmaf(d0, a0.x, fmaf(d1, b0.x, p0[0]));
            p0[1] = fmaf(d0, a0.y, fmaf(d1, b0.y, p0[1]));
            p0[2] = fmaf(d0, a0.z, fmaf(d1, b0.z, p0[2]));
            p0[3] = fmaf(d0, a0.w, fmaf(d1, b0.w, p0[3]));
            p0[4] = fmaf(d0, a1.x, fmaf(d1, b1.x, p0[4]));
            p0[5] = fmaf(d0, a1.y, fmaf(d1, b1.y, p0[5]));
            p0[6] = fmaf(d0, a1.z, fmaf(d1, b1.z, p0[6]));
            p0[7] = fmaf(d0, a1.w, fmaf(d1, b1.w, p0[7]));
            p1[0] = fmaf(d2, a0.x, fmaf(d3, b0.x, p1[0]));
            p1[1] = fmaf(d2, a0.y, fmaf(d3, b0.y, p1[1]));
            p1[2] = fmaf(d2, a0.z, fmaf(d3, b0.z, p1[2]));
            p1[3] = fmaf(d2, a0.w, fmaf(d3, b0.w, p1[3]));
            p1[4] = fmaf(d2, a1.x, fmaf(d3, b1.x, p1[4]));
            p1[5] = fmaf(d2, a1.y, fmaf(d3, b1.y, p1[5]));
            p1[6] = fmaf(d2, a1.z, fmaf(d3, b1.z, p1[6]));
            p1[7] = fmaf(d2, a1.w, fmaf(d3, b1.w, p1[7]));
        }
    #pragma unroll
    for (int off = 1; off <= 2; off <<= 1)
        #pragma unroll
        for (int s = 0; s < 4; ++s)
            #pragma unroll
            for (int h = 0; h < 8; ++h)
                pa[s][h] += __shfl_xor_sync(0xffffffffu, pa[s][h], off);
    if (tig == 0) {
        #pragma unroll
        for (int s = 0; s < 4; ++s) {
            const int row = mw * 32 + (s >> 1) * 16 + (s & 1) * 8 + g;
            #pragma unroll
            for (int h = 0; h < 8; ++h)
                atomicAdd(&alpha_sm[row * 8 + h], pa[s][h]);
        }
    }
    __syncthreads();

    const int row = t >> 3, h = t & 7;
    const int m = m0 + row;
    if (m < n) g_alpha[(size_t)m * 8 + h] = alpha_sm[row * 8 + h];
}

// ---------------------------------------------------------------------------
// k_stats: per graph: softmax stats; overwrite g_alpha with normalized gates;
// zero out[b].
// ---------------------------------------------------------------------------
__global__ __launch_bounds__(256)
void k_stats(const int* __restrict__ batch,
             float* __restrict__ out,
             int n)
{
    const int b = blockIdx.x;
    const int t = threadIdx.x;

    int lo, hi;
    {
        int l = 0, r2 = n;
        while (l < r2) { int mid = (l + r2) >> 1; if (batch[mid] < b) l = mid + 1; else r2 = mid; }
        lo = l;
        r2 = n;
        while (l < r2) { int mid = (l + r2) >> 1; if (batch[mid] < b + 1) l = mid + 1; else r2 = mid; }
        hi = l;
    }

    __shared__ float red[256][8];
    __shared__ float mh[8];
    __shared__ float ih[8];

    float lm[8];
    #pragma unroll
    for (int q = 0; q < 8; ++q) lm[q] = -1e30f;
    for (int i = lo + t; i < hi; i += 256) {
        #pragma unroll
        for (int q = 0; q < 8; ++q)
            lm[q] = fmaxf(lm[q], g_alpha[(size_t)i * 8 + q]);
    }
    #pragma unroll
    for (int q = 0; q < 8; ++q) red[t][q] = lm[q];
    __syncthreads();
    for (int s2 = 128; s2 > 0; s2 >>= 1) {
        if (t < s2) {
            #pragma unroll
            for (int q = 0; q < 8; ++q)
                red[t][q] = fmaxf(red[t][q], red[t + s2][q]);
        }
        __syncthreads();
    }
    if (t < 8) mh[t] = red[0][t];
    __syncthreads();

    float m8[8];
    #pragma unroll
    for (int q = 0; q < 8; ++q) m8[q] = mh[q];

    float ls[8];
    #pragma unroll
    for (int q = 0; q < 8; ++q) ls[q] = 0.f;
    for (int i = lo + t; i < hi; i += 256) {
        #pragma unroll
        for (int q = 0; q < 8; ++q)
            ls[q] += __expf(g_alpha[(size_t)i * 8 + q] - m8[q]);
    }
    __syncthreads();
    #pragma unroll
    for (int q = 0; q < 8; ++q) red[t][q] = ls[q];
    __syncthreads();
    for (int s2 = 128; s2 > 0; s2 >>= 1) {
        if (t < s2) {
            #pragma unroll
            for (int q = 0; q < 8; ++q)
                red[t][q] += red[t + s2][q];
        }
        __syncthreads();
    }
    if (t < 8) ih[t] = 1.f / (red[0][t] + 1e-16f);
    __syncthreads();

    float i8[8];
    #pragma unroll
    for (int q = 0; q < 8; ++q) i8[q] = ih[q];

    // overwrite alpha with gates
    for (long long e = (long long)lo * 8 + t; e < (long long)hi * 8; e += 256) {
        const int h = (int)(e & 7);
        g_alpha[e] = __expf(g_alpha[e] - m8[h]) * i8[h];
    }
    // zero output row (atomic target)
    out[(size_t)b * 256 + t] = 0.f;
}

// ---------------------------------------------------------------------------
// k_feat2: feats = relu(x@Wn1+b1)@Wn2 + b2, gated per-node, reduced per graph
// within the 64-row tile, atomicAdd into out.
// ---------------------------------------------------------------------------
__global__ __launch_bounds__(512, 1)
void k_feat2(const float* __restrict__ x,
             const int* __restrict__ batch,
             const float* __restrict__ bn1,
             const float* __restrict__ bn2,
             float* __restrict__ out,
             int n)
{
    extern __shared__ unsigned char sm[];
    const uint32_t sb = smem_u32(sm);
    float* b1s = (float*)(sm + OFF_B1);
    float* b2s = (float*)(sm + OFF_B2);
    int*   bbs = (int*)(sm + OFF_BB);

    const int t = threadIdx.x;
    const int lane = t & 31, w = t >> 5;
    const int g = lane >> 2, tig = lane & 3;
    const int m0 = blockIdx.x * 64;

    if (t < 256) { b1s[t] = bn1[t]; b2s[t] = bn2[t]; }
    if (t < 64) bbs[t] = (m0 + t < n) ? batch[m0 + t] : -1;
    stage_x(x, sm, m0, n, t);
    __syncthreads();

    // ---- stage 1: D1 = x @ Wn1 ----
    const int mw = w & 1, nw = w >> 1;
    float acc[4][2][4];
    #pragma unroll
    for (int j = 0; j < 4; ++j)
        #pragma unroll
        for (int mf = 0; mf < 2; ++mf)
            #pragma unroll
            for (int q = 0; q < 4; ++q) acc[j][mf][q] = 0.f;

    gemm_tile(sb, 0, mw, nw, lane, acc);   // image 0 = W_n1
    __syncthreads();                       // A reads done; reuse region for H

    // ---- H = relu(D1 + b1) -> bf16 hi/lo smem (same region/pitch) ----
    #pragma unroll
    for (int mf = 0; mf < 2; ++mf)
        #pragma unroll
        for (int j = 0; j < 4; ++j) {
            const int c  = nw * 32 + j * 8 + tig * 2;
            const int r0 = mw * 32 + mf * 16 + g;
            const int r1 = r0 + 8;
            const float v0 = fmaxf(acc[j][mf][0] + b1s[c],     0.f);
            const float v1 = fmaxf(acc[j][mf][1] + b1s[c + 1], 0.f);
            const float v2 = fmaxf(acc[j][mf][2] + b1s[c],     0.f);
            const float v3 = fmaxf(acc[j][mf][3] + b1s[c + 1], 0.f);
            uint16_t h0, h1, h2, h3, l0, l1, l2, l3;
            split_bf16(v0, h0, l0);
            split_bf16(v1, h1, l1);
            split_bf16(v2, h2, l2);
            split_bf16(v3, h3, l3);
            *(uint32_t*)(sm + OFF_AH + r0 * P_A + c * 2) = (uint32_t)h0 | ((uint32_t)h1 << 16);
            *(uint32_t*)(sm + OFF_AL + r0 * P_A + c * 2) = (uint32_t)l0 | ((uint32_t)l1 << 16);
            *(uint32_t*)(sm + OFF_AH + r1 * P_A + c * 2) = (uint32_t)h2 | ((uint32_t)h3 << 16);
            *(uint32_t*)(sm + OFF_AL + r1 * P_A + c * 2) = (uint32_t)l2 | ((uint32_t)l3 << 16);
        }
    __syncthreads();

    // ---- stage 2: D2 = H @ Wn2 ----
    const int mw2 = w & 3, nw2 = w >> 2;
    float acc2[8][4];
    #pragma unroll
    for (int j = 0; j < 8; ++j)
        #pragma unroll
        for (int q = 0; q < 4; ++q) acc2[j][q] = 0.f;

    #pragma unroll
    for (int ks = 0; ks < 16; ++ks) {
        const uint32_t hbase = sb + (mw2 * 16 + (lane & 15)) * P_A
                               + ks * 32 + ((lane >> 4) << 4);
        uint32_t ah[4], al[4];
        ldsm4(ah, hbase + OFF_AH);
        ldsm4(al, hbase + OFF_AL);
        const int fb = ((2 * 32 + ks) * 32 + nw2 * 8) * 32 + lane;
        #pragma unroll
        for (int j = 0; j < 8; ++j) {
            const uint2 bh = __ldg(&g_Wfrag[fb + j * 32]);
            const uint2 bl = __ldg(&g_Wfrag[fb + 16384 + j * 32]);
            mma16816(acc2[j], ah, bh);
            mma16816(acc2[j], ah, bl);
            mma16816(acc2[j], al, bh);
        }
    }
    __syncthreads();   // H reads done; reuse region for weighted feats (fp32)

    // ---- weighted feats -> smem Wf[64][256] (pitch P_WF) ----
    {
        const int r0 = mw2 * 16 + g;
        const int r1 = r0 + 8;
        float2 g0 = make_float2(0.f, 0.f), g1 = make_float2(0.f, 0.f);
        if (m0 + r0 < n) g0 = *(const float2*)(g_alpha + (size_t)(m0 + r0) * 8 + tig * 2);
        if (m0 + r1 < n) g1 = *(const float2*)(g_alpha + (size_t)(m0 + r1) * 8 + tig * 2);
        #pragma unroll
        for (int j = 0; j < 8; ++j) {
            const int c = nw2 * 64 + j * 8 + tig * 2;
            float2 s0, s1;
            s0.x = (acc2[j][0] + b2s[c])     * g0.x;
            s0.y = (acc2[j][1] + b2s[c + 1]) * g0.y;
            s1.x = (acc2[j][2] + b2s[c])     * g1.x;
            s1.y = (acc2[j][3] + b2s[c + 1]) * g1.y;
            *(float2*)(sm + OFF_AH + r0 * P_WF + c * 4) = s0;
            *(float2*)(sm + OFF_AH + r1 * P_WF + c * 4) = s1;
        }
    }
    __syncthreads();

    // ---- segmented reduction over rows (sorted batch) -> atomicAdd out ----
    {
        const int c = t & 255;
        const int half = t >> 8;
        float s = 0.f;
        int cur = -1;
        const int rend = half * 32 + 32;
        for (int r = half * 32; r < rend; ++r) {
            if (m0 + r >= n) break;
            const int gid = bbs[r];
            if (gid != cur) {
                if (cur >= 0) atomicAdd(out + (size_t)cur * 256 + c, s);
                cur = gid;
                s = 0.f;
            }
            s += *(const float*)(sm + OFF_AH + r * P_WF + c * 4);
        }
        if (cur >= 0) atomicAdd(out + (size_t)cur * 256 + c, s);
    }
}

// ---------------------------------------------------------------------------
extern "C" void kernel_launch(void* const* d_in, const int* in_sizes, int n_in,
                              void* d_out, int out_size)
{
    const float* x     = (const float*)d_in[0];
    const int*   batch = (const int*)d_in[1];
    const float* Wg1   = (const float*)d_in[2];
    const float* Wg2   = (const float*)d_in[3];
    const float* Wn1   = (const float*)d_in[4];
    const float* bn1   = (const float*)d_in[5];
    const float* Wn2   = (const float*)d_in[6];
    const float* bn2   = (const float*)d_in[7];
    float* out = (float*)d_out;

    const int n = in_sizes[0] / 256;
    const int B = out_size / 256;
    const int tiles = (n + 63) / 64;

    cudaFuncSetAttribute(k_alpha, cudaFuncAttributeMaxDynamicSharedMemorySize, SMEM_ALPHA);
    cudaFuncSetAttribute(k_feat2, cudaFuncAttributeMaxDynamicSharedMemorySize, SMEM_FEAT);

    k_prep<<<dim3(64, 3), 256>>>(Wn1, Wg1, Wn2);
    k_alpha<<<tiles, 512, SMEM_ALPHA>>>(x, Wg2, n);
    k_stats<<<B, 256>>>(batch, out, n);
    k_feat2<<<tiles, 512, SMEM_FEAT>>>(x, batch, bn1, bn2, out, n);
}

// round 6
// speedup vs baseline: 3.1965x; 1.0870x over previous
#include <cuda_runtime.h>
#include <cuda_bf16.h>
#include <cstdint>
#include <cstddef>

// ---------------------------------------------------------------------------
//   x[N,256], batch[N] int32 sorted, W_g1[256,256], W_g2[256,8],
//   W_n1[256,256], b_n1[256], W_n2[256,256], b_n2[256] -> out[1024,256] fp32
//   Engine: mma.sync m16n8k16 bf16 hi/lo 3-pass.
//   k1: x @ [Wn1|Wg1] fused (N=512); alpha -> g_alpha; H -> g_H in MMA
//       A-fragment order (bf16 hi/lo). k_stats: gates in place. k2: H@Wn2,
//       gated per-graph reduce (no smem staging / no ldmatrix in mainloop).
// ---------------------------------------------------------------------------

#define N_MAX 200000
#define MAX_TILES ((N_MAX + 63) / 64)

__device__ float g_alpha[(size_t)N_MAX * 8];    // alpha, then gates (in-place)
// fragment-ordered weights: [w(3)][hl(2)][kstep(16)][nfrag(32)][lane(32)] uint2
__device__ uint2 g_Wfrag[3 * 2 * 16 * 32 * 32];
// H in A-fragment order: [tb(4/tile)][kb(16)][hl(2)][lane(32)] uint4
__device__ uint4 g_H[(size_t)MAX_TILES * 4 * 16 * 2 * 32];

// ---------------- helpers ---------------------------------------------------
__device__ __forceinline__ uint32_t smem_u32(const void* p) {
    uint32_t a;
    asm("{ .reg .u64 t; cvta.to.shared.u64 t, %1; cvt.u32.u64 %0, t; }"
        : "=r"(a) : "l"(p));
    return a;
}
__device__ __forceinline__ void split_bf16(float v, uint16_t& h, uint16_t& l) {
    __nv_bfloat16 hb = __float2bfloat16(v);
    h = __bfloat16_as_ushort(hb);
    l = __bfloat16_as_ushort(__float2bfloat16(v - __bfloat162float(hb)));
}
__device__ __forceinline__ void ldsm4(uint32_t* a, uint32_t addr) {
    asm volatile("ldmatrix.sync.aligned.m8n8.x4.shared.b16 {%0,%1,%2,%3}, [%4];"
                 : "=r"(a[0]), "=r"(a[1]), "=r"(a[2]), "=r"(a[3]) : "r"(addr));
}
__device__ __forceinline__ void mma16816(float* c, const uint32_t* a, uint2 b) {
    asm volatile(
        "mma.sync.aligned.m16n8k16.row.col.f32.bf16.bf16.f32 "
        "{%0,%1,%2,%3},{%4,%5,%6,%7},{%8,%9},{%0,%1,%2,%3};"
        : "+f"(c[0]), "+f"(c[1]), "+f"(c[2]), "+f"(c[3])
        : "r"(a[0]), "r"(a[1]), "r"(a[2]), "r"(a[3]), "r"(b.x), "r"(b.y));
}

// ---------------- smem layouts (bytes) --------------------------------------
#define P_A 528                    // bf16 tile pitch: 64 rows x 256 cols + pad
#define OFF_AH   0                 // 33792
#define OFF_AL   33792             // 33792
#define OFF_WG2  67584             // 8192
#define OFF_ALP  75776             // 2048
#define OFF_B1K  77824             // 1024
#define SMEM_K1  78848

#define P_WF 1032                  // fp32 weighted-feats pitch
#define OFF_WF   0                 // 64*1032 = 66048
#define OFF_B2K  66048             // 1024
#define OFF_BBK  67072             // 256
#define SMEM_K2  67328

// ---------------------------------------------------------------------------
// k_prep: pack 3 weights into fragment-ordered bf16 hi/lo uint2 arrays.
// ---------------------------------------------------------------------------
__global__ void k_prep(const float* __restrict__ Wn1,
                       const float* __restrict__ Wg1,
                       const float* __restrict__ Wn2)
{
    const float* W = (blockIdx.y == 0) ? Wn1 : (blockIdx.y == 1) ? Wg1 : Wn2;
    const int i = blockIdx.x * 256 + threadIdx.x;
    const int lane = i & 31;
    const int nf   = (i >> 5) & 31;
    const int ks   = i >> 10;
    const int nn   = nf * 8 + (lane >> 2);
    const int k0   = ks * 16 + (lane & 3) * 2;

    float v[4];
    v[0] = W[(k0 + 0) * 256 + nn];
    v[1] = W[(k0 + 1) * 256 + nn];
    v[2] = W[(k0 + 8) * 256 + nn];
    v[3] = W[(k0 + 9) * 256 + nn];

    uint16_t h[4], l[4];
    #pragma unroll
    for (int q = 0; q < 4; ++q) split_bf16(v[q], h[q], l[q]);
    uint2 hi, lo;
    hi.x = (uint32_t)h[0] | ((uint32_t)h[1] << 16);
    hi.y = (uint32_t)h[2] | ((uint32_t)h[3] << 16);
    lo.x = (uint32_t)l[0] | ((uint32_t)l[1] << 16);
    lo.y = (uint32_t)l[2] | ((uint32_t)l[3] << 16);

    const int w = blockIdx.y;
    g_Wfrag[((((w * 2 + 0) * 16 + ks) * 32 + nf) * 32) + lane] = hi;
    g_Wfrag[((((w * 2 + 1) * 16 + ks) * 32 + nf) * 32) + lane] = lo;
}

// stage x[m0:m0+64, 0:256] into bf16 hi/lo smem (pitch P_A)
__device__ __forceinline__ void stage_x(const float* __restrict__ x,
                                        unsigned char* sm, int m0, int n, int t)
{
    #pragma unroll
    for (int e = 0; e < 8; ++e) {
        const int idx = t + e * 512;
        const int row = idx >> 6, q = idx & 63;
        const int m = m0 + row;
        float4 v = make_float4(0.f, 0.f, 0.f, 0.f);
        if (m < n) v = ((const float4*)(x + (size_t)m * 256))[q];
        uint16_t h0, h1, h2, h3, l0, l1, l2, l3;
        split_bf16(v.x, h0, l0);
        split_bf16(v.y, h1, l1);
        split_bf16(v.z, h2, l2);
        split_bf16(v.w, h3, l3);
        uint2 hp, lp;
        hp.x = (uint32_t)h0 | ((uint32_t)h1 << 16);
        hp.y = (uint32_t)h2 | ((uint32_t)h3 << 16);
        lp.x = (uint32_t)l0 | ((uint32_t)l1 << 16);
        lp.y = (uint32_t)l2 | ((uint32_t)l3 << 16);
        *(uint2*)(sm + OFF_AH + row * P_A + q * 8) = hp;
        *(uint2*)(sm + OFF_AL + row * P_A + q * 8) = lp;
    }
}

// ---------------------------------------------------------------------------
// k1: D[64,512] = x @ [Wn1 | Wg1] (3-pass). Warps nw 0..3 -> H fragments to
// g_H; warps nw 4..7 -> alpha = relu(D)@Wg2 -> g_alpha.
// ---------------------------------------------------------------------------
__global__ __launch_bounds__(512, 1)
void k1(const float* __restrict__ x,
        const float* __restrict__ Wg2,
        const float* __restrict__ bn1,
        int n)
{
    extern __shared__ unsigned char sm[];
    const uint32_t sb = smem_u32(sm);
    float* Wg2s     = (float*)(sm + OFF_WG2);
    float* alpha_sm = (float*)(sm + OFF_ALP);
    float* b1s      = (float*)(sm + OFF_B1K);

    const int t = threadIdx.x;
    const int lane = t & 31, w = t >> 5;
    const int g = lane >> 2, tig = lane & 3;
    const int m0 = blockIdx.x * 64;
    const int mw = w & 1, nw = w >> 1;

    #pragma unroll
    for (int q = 0; q < 4; ++q) Wg2s[t + q * 512] = Wg2[t + q * 512];
    if (t < 256) b1s[t] = bn1[t];
    alpha_sm[t] = 0.f;
    stage_x(x, sm, m0, n, t);
    __syncthreads();

    // warp-tile 32x64: acc[j 0..7][mf 0..1][4]
    float acc[8][2][4];
    #pragma unroll
    for (int j = 0; j < 8; ++j)
        #pragma unroll
        for (int mf = 0; mf < 2; ++mf)
            #pragma unroll
            for (int q = 0; q < 4; ++q) acc[j][mf][q] = 0.f;

    const int img = (nw >= 4) ? 1 : 0;
    const int nb  = (nw & 3) * 8;

    #pragma unroll
    for (int ks = 0; ks < 16; ++ks) {
        const uint32_t abase = sb + (mw * 32 + (lane & 15)) * P_A
                               + ks * 32 + ((lane >> 4) << 4);
        uint32_t ah0[4], ah1[4], al0[4], al1[4];
        ldsm4(ah0, abase + OFF_AH);
        ldsm4(ah1, abase + OFF_AH + 16 * P_A);
        ldsm4(al0, abase + OFF_AL);
        ldsm4(al1, abase + OFF_AL + 16 * P_A);
        const int fb = ((img * 32 + ks) * 32 + nb) * 32 + lane;
        #pragma unroll
        for (int j = 0; j < 8; ++j) {
            const uint2 bh = __ldg(&g_Wfrag[fb + j * 32]);
            const uint2 bl = __ldg(&g_Wfrag[fb + 16384 + j * 32]);
            mma16816(acc[j][0], ah0, bh);
            mma16816(acc[j][1], ah1, bh);
            mma16816(acc[j][0], ah0, bl);
            mma16816(acc[j][1], ah1, bl);
            mma16816(acc[j][0], al0, bh);
            mma16816(acc[j][1], al1, bh);
        }
    }

    if (nw < 4) {
        // ---- H = relu(D + b1): write in A-fragment order (hi/lo) ----
        #pragma unroll
        for (int mf = 0; mf < 2; ++mf) {
            const size_t tb = (size_t)(blockIdx.x * 4 + mw * 2 + mf);
            #pragma unroll
            for (int kp = 0; kp < 4; ++kp) {
                const int kb = nw * 4 + kp;
                uint4 Hh, Hl;
                #pragma unroll
                for (int je = 0; je < 2; ++je) {
                    const int j = kp * 2 + je;
                    const int c = nw * 64 + j * 8 + tig * 2;
                    const float v0 = fmaxf(acc[j][mf][0] + b1s[c],     0.f);
                    const float v1 = fmaxf(acc[j][mf][1] + b1s[c + 1], 0.f);
                    const float v2 = fmaxf(acc[j][mf][2] + b1s[c],     0.f);
                    const float v3 = fmaxf(acc[j][mf][3] + b1s[c + 1], 0.f);
                    uint16_t h0, h1, h2, h3, l0, l1, l2, l3;
                    split_bf16(v0, h0, l0);
                    split_bf16(v1, h1, l1);
                    split_bf16(v2, h2, l2);
                    split_bf16(v3, h3, l3);
                    const uint32_t hp0 = (uint32_t)h0 | ((uint32_t)h1 << 16);
                    const uint32_t hp1 = (uint32_t)h2 | ((uint32_t)h3 << 16);
                    const uint32_t lp0 = (uint32_t)l0 | ((uint32_t)l1 << 16);
                    const uint32_t lp1 = (uint32_t)l2 | ((uint32_t)l3 << 16);
                    if (je == 0) { Hh.x = hp0; Hh.y = hp1; Hl.x = lp0; Hl.y = lp1; }
                    else         { Hh.z = hp0; Hh.w = hp1; Hl.z = lp0; Hl.w = lp1; }
                }
                const size_t base = ((tb * 16 + kb) * 2) * 32 + lane;
                g_H[base]      = Hh;
                g_H[base + 32] = Hl;
            }
        }
    } else {
        // ---- alpha partial = relu(D) @ Wg2 over this warp's 64-col slice ----
        float pa[4][8];
        #pragma unroll
        for (int s = 0; s < 4; ++s)
            #pragma unroll
            for (int h = 0; h < 8; ++h) pa[s][h] = 0.f;

        #pragma unroll
        for (int mf = 0; mf < 2; ++mf)
            #pragma unroll
            for (int j = 0; j < 8; ++j) {
                const int c = (nw - 4) * 64 + j * 8 + tig * 2;
                const float d0 = fmaxf(acc[j][mf][0], 0.f);
                const float d1 = fmaxf(acc[j][mf][1], 0.f);
                const float d2 = fmaxf(acc[j][mf][2], 0.f);
                const float d3 = fmaxf(acc[j][mf][3], 0.f);
                const float4* wa = (const float4*)(Wg2s + c * 8);
                const float4* wb = (const float4*)(Wg2s + (c + 1) * 8);
                const float4 a0 = wa[0], a1 = wa[1], b0 = wb[0], b1 = wb[1];
                float* p0 = pa[mf * 2];
                float* p1 = pa[mf * 2 + 1];
                p0[0] = fmaf(d0, a0.x, fmaf(d1, b0.x, p0[0]));
                p0[1] = fmaf(d0, a0.y, fmaf(d1, b0.y, p0[1]));
                p0[2] = fmaf(d0, a0.z, fmaf(d1, b0.z, p0[2]));
                p0[3] = fmaf(d0, a0.w, fmaf(d1, b0.w, p0[3]));
                p0[4] = fmaf(d0, a1.x, fmaf(d1, b1.x, p0[4]));
                p0[5] = fmaf(d0, a1.y, fmaf(d1, b1.y, p0[5]));
                p0[6] = fmaf(d0, a1.z, fmaf(d1, b1.z, p0[6]));
                p0[7] = fmaf(d0, a1.w, fmaf(d1, b1.w, p0[7]));
                p1[0] = fmaf(d2, a0.x, fmaf(d3, b0.x, p1[0]));
                p1[1] = fmaf(d2, a0.y, fmaf(d3, b0.y, p1[1]));
                p1[2] = fmaf(d2, a0.z, fmaf(d3, b0.z, p1[2]));
                p1[3] = fmaf(d2, a0.w, fmaf(d3, b0.w, p1[3]));
                p1[4] = fmaf(d2, a1.x, fmaf(d3, b1.x, p1[4]));
                p1[5] = fmaf(d2, a1.y, fmaf(d3, b1.y, p1[5]));
                p1[6] = fmaf(d2, a1.z, fmaf(d3, b1.z, p1[6]));
                p1[7] = fmaf(d2, a1.w, fmaf(d3, b1.w, p1[7]));
            }
        #pragma unroll
        for (int off = 1; off <= 2; off <<= 1)
            #pragma unroll
            for (int s = 0; s < 4; ++s)
                #pragma unroll
                for (int h = 0; h < 8; ++h)
                    pa[s][h] += __shfl_xor_sync(0xffffffffu, pa[s][h], off);
        if (tig == 0) {
            #pragma unroll
            for (int s = 0; s < 4; ++s) {
                const int row = mw * 32 + (s >> 1) * 16 + (s & 1) * 8 + g;
                #pragma unroll
                for (int h = 0; h < 8; ++h)
                    atomicAdd(&alpha_sm[row * 8 + h], pa[s][h]);
            }
        }
    }
    __syncthreads();

    const int row = t >> 3, h = t & 7;
    const int m = m0 + row;
    if (m < n) g_alpha[(size_t)m * 8 + h] = alpha_sm[row * 8 + h];
}

// ---------------------------------------------------------------------------
// k_stats: per graph softmax stats; overwrite g_alpha with gates; zero out.
// ---------------------------------------------------------------------------
__global__ __launch_bounds__(256)
void k_stats(const int* __restrict__ batch,
             float* __restrict__ out,
             int n)
{
    const int b = blockIdx.x;
    const int t = threadIdx.x;

    int lo, hi;
    {
        int l = 0, r2 = n;
        while (l < r2) { int mid = (l + r2) >> 1; if (batch[mid] < b) l = mid + 1; else r2 = mid; }
        lo = l;
        r2 = n;
        while (l < r2) { int mid = (l + r2) >> 1; if (batch[mid] < b + 1) l = mid + 1; else r2 = mid; }
        hi = l;
    }

    __shared__ float red[256][8];
    __shared__ float mh[8];
    __shared__ float ih[8];

    float lm[8];
    #pragma unroll
    for (int q = 0; q < 8; ++q) lm[q] = -1e30f;
    for (int i = lo + t; i < hi; i += 256) {
        #pragma unroll
        for (int q = 0; q < 8; ++q)
            lm[q] = fmaxf(lm[q], g_alpha[(size_t)i * 8 + q]);
    }
    #pragma unroll
    for (int q = 0; q < 8; ++q) red[t][q] = lm[q];
    __syncthreads();
    for (int s2 = 128; s2 > 0; s2 >>= 1) {
        if (t < s2) {
            #pragma unroll
            for (int q = 0; q < 8; ++q)
                red[t][q] = fmaxf(red[t][q], red[t + s2][q]);
        }
        __syncthreads();
    }
    if (t < 8) mh[t] = red[0][t];
    __syncthreads();

    float m8[8];
    #pragma unroll
    for (int q = 0; q < 8; ++q) m8[q] = mh[q];

    float ls[8];
    #pragma unroll
    for (int q = 0; q < 8; ++q) ls[q] = 0.f;
    for (int i = lo + t; i < hi; i += 256) {
        #pragma unroll
        for (int q = 0; q < 8; ++q)
            ls[q] += __expf(g_alpha[(size_t)i * 8 + q] - m8[q]);
    }
    __syncthreads();
    #pragma unroll
    for (int q = 0; q < 8; ++q) red[t][q] = ls[q];
    __syncthreads();
    for (int s2 = 128; s2 > 0; s2 >>= 1) {
        if (t < s2) {
            #pragma unroll
            for (int q = 0; q < 8; ++q)
                red[t][q] += red[t + s2][q];
        }
        __syncthreads();
    }
    if (t < 8) ih[t] = 1.f / (red[0][t] + 1e-16f);
    __syncthreads();

    float i8[8];
    #pragma unroll
    for (int q = 0; q < 8; ++q) i8[q] = ih[q];

    for (long long e = (long long)lo * 8 + t; e < (long long)hi * 8; e += 256) {
        const int h = (int)(e & 7);
        g_alpha[e] = __expf(g_alpha[e] - m8[h]) * i8[h];
    }
    out[(size_t)b * 256 + t] = 0.f;
}

// ---------------------------------------------------------------------------
// k2: D2 = H @ Wn2 (+b2), gate-weight, tile-local segmented reduce, atomics.
// A fragments come straight from g_H (LDG.128) — no smem staging, no ldsm.
// ---------------------------------------------------------------------------
__global__ __launch_bounds__(512, 1)
void k2(const int* __restrict__ batch,
        const float* __restrict__ bn2,
        float* __restrict__ out,
        int n)
{
    extern __shared__ unsigned char sm[];
    float* b2s = (float*)(sm + OFF_B2K);
    int*   bbs = (int*)(sm + OFF_BBK);

    const int t = threadIdx.x;
    const int lane = t & 31, w = t >> 5;
    const int g = lane >> 2, tig = lane & 3;
    const int m0 = blockIdx.x * 64;
    const int mw2 = w & 3, nw2 = w >> 2;

    if (t < 256) b2s[t] = bn2[t];
    if (t < 64) bbs[t] = (m0 + t < n) ? batch[m0 + t] : -1;
    __syncthreads();

    float acc2[8][4];
    #pragma unroll
    for (int j = 0; j < 8; ++j)
        #pragma unroll
        for (int q = 0; q < 4; ++q) acc2[j][q] = 0.f;

    const size_t tb = (size_t)(blockIdx.x * 4 + mw2);
    #pragma unroll
    for (int kb = 0; kb < 16; ++kb) {
        const size_t base = ((tb * 16 + kb) * 2) * 32 + lane;
        const uint4 Hh = __ldg(&g_H[base]);
        const uint4 Hl = __ldg(&g_H[base + 32]);
        uint32_t ah[4] = {Hh.x, Hh.y, Hh.z, Hh.w};
        uint32_t al[4] = {Hl.x, Hl.y, Hl.z, Hl.w};
        const int fb = ((2 * 32 + kb) * 32 + nw2 * 8) * 32 + lane;
        #pragma unroll
        for (int j = 0; j < 8; ++j) {
            const uint2 bh = __ldg(&g_Wfrag[fb + j * 32]);
            const uint2 bl = __ldg(&g_Wfrag[fb + 16384 + j * 32]);
            mma16816(acc2[j], ah, bh);
            mma16816(acc2[j], ah, bl);
            mma16816(acc2[j], al, bh);
        }
    }

    // ---- weighted feats -> smem Wf[64][256] ----
    {
        const int r0 = mw2 * 16 + g;
        const int r1 = r0 + 8;
        float2 g0 = make_float2(0.f, 0.f), g1 = make_float2(0.f, 0.f);
        if (m0 + r0 < n) g0 = *(const float2*)(g_alpha + (size_t)(m0 + r0) * 8 + tig * 2);
        if (m0 + r1 < n) g1 = *(const float2*)(g_alpha + (size_t)(m0 + r1) * 8 + tig * 2);
        #pragma unroll
        for (int j = 0; j < 8; ++j) {
            const int c = nw2 * 64 + j * 8 + tig * 2;
            float2 s0, s1;
            s0.x = (acc2[j][0] + b2s[c])     * g0.x;
            s0.y = (acc2[j][1] + b2s[c + 1]) * g0.y;
            s1.x = (acc2[j][2] + b2s[c])     * g1.x;
            s1.y = (acc2[j][3] + b2s[c + 1]) * g1.y;
            *(float2*)(sm + OFF_WF + r0 * P_WF + c * 4) = s0;
            *(float2*)(sm + OFF_WF + r1 * P_WF + c * 4) = s1;
        }
    }
    __syncthreads();

    // ---- segmented reduction over rows (sorted batch) -> atomicAdd out ----
    {
        const int c = t & 255;
        const int half = t >> 8;
        float s = 0.f;
        int cur = -1;
        const int rend = half * 32 + 32;
        for (int r = half * 32; r < rend; ++r) {
            if (m0 + r >= n) break;
            const int gid = bbs[r];
            if (gid != cur) {
                if (cur >= 0) atomicAdd(out + (size_t)cur * 256 + c, s);
                cur = gid;
                s = 0.f;
            }
            s += *(const float*)(sm + OFF_WF + r * P_WF + c * 4);
        }
        if (cur >= 0) atomicAdd(out + (size_t)cur * 256 + c, s);
    }
}

// ---------------------------------------------------------------------------
extern "C" void kernel_launch(void* const* d_in, const int* in_sizes, int n_in,
                              void* d_out, int out_size)
{
    const float* x     = (const float*)d_in[0];
    const int*   batch = (const int*)d_in[1];
    const float* Wg1   = (const float*)d_in[2];
    const float* Wg2   = (const float*)d_in[3];
    const float* Wn1   = (const float*)d_in[4];
    const float* bn1   = (const float*)d_in[5];
    const float* Wn2   = (const float*)d_in[6];
    const float* bn2   = (const float*)d_in[7];
    float* out = (float*)d_out;

    const int n = in_sizes[0] / 256;
    const int B = out_size / 256;
    const int tiles = (n + 63) / 64;

    cudaFuncSetAttribute(k1, cudaFuncAttributeMaxDynamicSharedMemorySize, SMEM_K1);
    cudaFuncSetAttribute(k2, cudaFuncAttributeMaxDynamicSharedMemorySize, SMEM_K2);

    k_prep<<<dim3(64, 3), 256>>>(Wn1, Wg1, Wn2);
    k1<<<tiles, 512, SMEM_K1>>>(x, Wg2, bn1, n);
    k_stats<<<B, 256>>>(batch, out, n);
    k2<<<tiles, 512, SMEM_K2>>>(batch, bn2, out, n);
}